// round 5
// baseline (speedup 1.0000x reference)
#include <cuda_runtime.h>
#include <cuda_bf16.h>
#include <math.h>
#include <stdint.h>

// Problem constants
#define BATCH 4
#define SEQ   2048
#define DM    1024
#define NH    16
#define DK    64
#define MROWS (BATCH * SEQ)      // 8192

// ---------------- scratch (device globals; no runtime alloc) ----------------
__device__ float g_q[MROWS * DM];
__device__ float g_k[MROWS * DM];
__device__ float g_v[MROWS * DM];
__device__ float g_attn[MROWS * DM];

// ---------------- helpers ----------------------------------------------------
__device__ __forceinline__ float to_tf32(float x) {
    uint32_t u;
    asm("cvt.rna.tf32.f32 %0, %1;" : "=r"(u) : "f"(x));
    return __uint_as_float(u);
}
__device__ __forceinline__ float fast_exp2(float x) {
    float y;
    asm("ex2.approx.f32 %0, %1;" : "=f"(y) : "f"(x));
    return y;
}
// D = A(16x8 tf32, row) * B(8x8 tf32, col) + C   (in-place C allowed)
__device__ __forceinline__ void mma_tf32(float* d, const uint32_t* a,
                                         const uint32_t* b, const float* c) {
    asm volatile(
        "mma.sync.aligned.m16n8k8.row.col.f32.tf32.tf32.f32 "
        "{%0,%1,%2,%3}, {%4,%5,%6,%7}, {%8,%9}, {%10,%11,%12,%13};\n"
        : "=f"(d[0]), "=f"(d[1]), "=f"(d[2]), "=f"(d[3])
        : "r"(a[0]), "r"(a[1]), "r"(a[2]), "r"(a[3]),
          "r"(b[0]), "r"(b[1]),
          "f"(c[0]), "f"(c[1]), "f"(c[2]), "f"(c[3]));
}

// ---------------- tf32 GEMM with bias: C = A[M,K] @ W[K,N] + b ---------------
// 128x128x32 tile, 256 threads (8 warps, 2x4), warp tile 64x32.
// Register-prefetch pipeline: LDG of tile t+1 issued before compute of tile t.
#define APAD 36
#define BPAD 136

__global__ __launch_bounds__(256) void gemm_bias_tf32(
    const float* __restrict__ A, const float* __restrict__ W,
    const float* __restrict__ bias, float* __restrict__ C,
    int M, int N, int K)
{
    __shared__ float As[128 * APAD];   // [m][k] pad 36
    __shared__ float Bs[32 * BPAD];    // [k][n] pad 136

    const int tid  = threadIdx.x;
    const int lane = tid & 31;
    const int warp = tid >> 5;
    const int g    = lane >> 2;
    const int tig  = lane & 3;
    const int wm   = warp >> 2;        // 0..1
    const int wn   = warp & 3;         // 0..3
    const int bm   = blockIdx.y * 128;
    const int bn   = blockIdx.x * 128;

    // load index mapping (per-thread, 4 iterations each)
    int ar[4], ac[4], br[4], bc[4];
    #pragma unroll
    for (int it = 0; it < 4; it++) {
        int idx = tid + 256 * it;
        ar[it] = idx >> 3;  ac[it] = (idx & 7) * 4;
        br[it] = idx >> 5;  bc[it] = (idx & 31) * 4;
    }

    float acc[4][4][4];
    #pragma unroll
    for (int mi = 0; mi < 4; mi++)
        #pragma unroll
        for (int ni = 0; ni < 4; ni++)
            #pragma unroll
            for (int q = 0; q < 4; q++) acc[mi][ni][q] = 0.f;

    // prologue: fetch k-tile 0
    float4 pa[4], pb[4];
    #pragma unroll
    for (int it = 0; it < 4; it++) {
        pa[it] = *(const float4*)&A[(size_t)(bm + ar[it]) * K + ac[it]];
        pb[it] = *(const float4*)&W[(size_t)br[it] * N + bn + bc[it]];
    }

    for (int k0 = 0; k0 < K; k0 += 32) {
        // commit prefetched tile to smem (tf32-converted)
        #pragma unroll
        for (int it = 0; it < 4; it++) {
            float* p = &As[ar[it] * APAD + ac[it]];
            p[0] = to_tf32(pa[it].x); p[1] = to_tf32(pa[it].y);
            p[2] = to_tf32(pa[it].z); p[3] = to_tf32(pa[it].w);
            float* q = &Bs[br[it] * BPAD + bc[it]];
            q[0] = to_tf32(pb[it].x); q[1] = to_tf32(pb[it].y);
            q[2] = to_tf32(pb[it].z); q[3] = to_tf32(pb[it].w);
        }
        __syncthreads();

        // issue next tile's loads; latency overlaps the MMAs below
        if (k0 + 32 < K) {
            #pragma unroll
            for (int it = 0; it < 4; it++) {
                pa[it] = *(const float4*)&A[(size_t)(bm + ar[it]) * K + k0 + 32 + ac[it]];
                pb[it] = *(const float4*)&W[(size_t)(k0 + 32 + br[it]) * N + bn + bc[it]];
            }
        }

        #pragma unroll
        for (int kk = 0; kk < 4; kk++) {
            uint32_t af[4][4];
            #pragma unroll
            for (int mi = 0; mi < 4; mi++) {
                const int m = wm * 64 + mi * 16;
                af[mi][0] = __float_as_uint(As[(m + g)     * APAD + kk * 8 + tig]);
                af[mi][1] = __float_as_uint(As[(m + g + 8) * APAD + kk * 8 + tig]);
                af[mi][2] = __float_as_uint(As[(m + g)     * APAD + kk * 8 + tig + 4]);
                af[mi][3] = __float_as_uint(As[(m + g + 8) * APAD + kk * 8 + tig + 4]);
            }
            #pragma unroll
            for (int ni = 0; ni < 4; ni++) {
                const int n = wn * 32 + ni * 8;
                uint32_t bf[2];
                bf[0] = __float_as_uint(Bs[(kk * 8 + tig)     * BPAD + n + g]);
                bf[1] = __float_as_uint(Bs[(kk * 8 + tig + 4) * BPAD + n + g]);
                #pragma unroll
                for (int mi = 0; mi < 4; mi++)
                    mma_tf32(acc[mi][ni], af[mi], bf, acc[mi][ni]);
            }
        }
        __syncthreads();
    }

    // epilogue: bias add, float2 stores
    #pragma unroll
    for (int mi = 0; mi < 4; mi++) {
        const int row = bm + wm * 64 + mi * 16 + g;
        #pragma unroll
        for (int ni = 0; ni < 4; ni++) {
            const int col = bn + wn * 32 + ni * 8 + 2 * tig;
            const float b0 = bias[col], b1 = bias[col + 1];
            float2 o0 = make_float2(acc[mi][ni][0] + b0, acc[mi][ni][1] + b1);
            float2 o1 = make_float2(acc[mi][ni][2] + b0, acc[mi][ni][3] + b1);
            *(float2*)&C[(size_t)row * N + col]       = o0;
            *(float2*)&C[(size_t)(row + 8) * N + col] = o1;
        }
    }
}

// ---------------- tf32 flash attention --------------------------------------
// Block: 128 threads (4 warps). BQ=64 (warp owns 16 rows), BKV=64.
// P never touches smem: score accum -> PV A-fragments via register shuffles.
// smem: Ks[64][76] (also used to stage Q once), Vs[64][72]
#define QPAD 76
#define VPAD 72
#define ATTN_SMEM ((64 * QPAD + 64 * VPAD) * sizeof(float))

__global__ __launch_bounds__(128) void attn_tf32(
    const float* __restrict__ gq, const float* __restrict__ gk,
    const float* __restrict__ gv, float* __restrict__ gout)
{
    extern __shared__ float smf[];
    float* Ks = smf;                   // [64][QPAD]
    float* Vs = Ks + 64 * QPAD;        // [64][VPAD]

    const int tid  = threadIdx.x;
    const int lane = tid & 31;
    const int warp = tid >> 5;         // 0..3
    const int g    = lane >> 2;
    const int tig  = lane & 3;
    const int q0   = blockIdx.x * 64;
    const int b    = blockIdx.y >> 4;
    const int h    = blockIdx.y & 15;

    const float* qb = gq + (size_t)b * SEQ * DM + (size_t)h * DK;
    const float* kb = gk + (size_t)b * SEQ * DM + (size_t)h * DK;
    const float* vb = gv + (size_t)b * SEQ * DM + (size_t)h * DK;

    // (1/sqrt(64)) * log2(e): softmax in base 2
    const float qscale = 0.125f * 1.44269504f;

    // Stage Q through Ks, pull fragments to registers (constant all KV tiles)
    for (int i = tid; i < 64 * 16; i += 128) {
        int r = i >> 4, c4 = (i & 15) * 4;
        float4 v = *(const float4*)&qb[(size_t)(q0 + r) * DM + c4];
        float* p = &Ks[r * QPAD + c4];
        p[0] = to_tf32(v.x * qscale); p[1] = to_tf32(v.y * qscale);
        p[2] = to_tf32(v.z * qscale); p[3] = to_tf32(v.w * qscale);
    }
    __syncthreads();

    const int m = warp * 16;
    uint32_t qa[8][4];
    #pragma unroll
    for (int kk = 0; kk < 8; kk++) {
        qa[kk][0] = __float_as_uint(Ks[(m + g)     * QPAD + kk * 8 + tig]);
        qa[kk][1] = __float_as_uint(Ks[(m + g + 8) * QPAD + kk * 8 + tig]);
        qa[kk][2] = __float_as_uint(Ks[(m + g)     * QPAD + kk * 8 + tig + 4]);
        qa[kk][3] = __float_as_uint(Ks[(m + g + 8) * QPAD + kk * 8 + tig + 4]);
    }

    float oa[8][4];
    #pragma unroll
    for (int ni = 0; ni < 8; ni++)
        #pragma unroll
        for (int q = 0; q < 4; q++) oa[ni][q] = 0.f;
    float mr0 = -1e30f, mr1 = -1e30f, lr0 = 0.f, lr1 = 0.f;

    const int srcA = (lane & ~3) | (tig >> 1);   // lane holding cols 2*(tig>>1)+{0,1}
    const int srcB = srcA + 2;                    // +4 cols
    const bool odd = tig & 1;

    for (int kt = 0; kt < SEQ / 64; kt++) {
        const int j0 = kt * 64;
        __syncthreads();   // prior tile fully consumed (incl. qa reads at kt=0)

        for (int i = tid; i < 64 * 16; i += 128) {
            int r = i >> 4, c4 = (i & 15) * 4;
            float4 kv = *(const float4*)&kb[(size_t)(j0 + r) * DM + c4];
            float4 vv = *(const float4*)&vb[(size_t)(j0 + r) * DM + c4];
            float* pk = &Ks[r * QPAD + c4];
            pk[0] = to_tf32(kv.x); pk[1] = to_tf32(kv.y);
            pk[2] = to_tf32(kv.z); pk[3] = to_tf32(kv.w);
            float* pv = &Vs[r * VPAD + c4];
            pv[0] = to_tf32(vv.x); pv[1] = to_tf32(vv.y);
            pv[2] = to_tf32(vv.z); pv[3] = to_tf32(vv.w);
        }
        __syncthreads();

        // ---- scores: S[r][j] (16 rows x 64 cols per warp) ----
        float sc[8][4];
        #pragma unroll
        for (int ni = 0; ni < 8; ni++)
            #pragma unroll
            for (int q = 0; q < 4; q++) sc[ni][q] = 0.f;

        #pragma unroll
        for (int kk = 0; kk < 8; kk++) {
            #pragma unroll
            for (int ni = 0; ni < 8; ni++) {
                uint32_t bf[2];
                bf[0] = __float_as_uint(Ks[(ni * 8 + g) * QPAD + kk * 8 + tig]);
                bf[1] = __float_as_uint(Ks[(ni * 8 + g) * QPAD + kk * 8 + tig + 4]);
                mma_tf32(sc[ni], qa[kk], bf, sc[ni]);
            }
        }

        // ---- online softmax (base 2) ----
        float rm0 = -1e30f, rm1 = -1e30f;
        #pragma unroll
        for (int ni = 0; ni < 8; ni++) {
            rm0 = fmaxf(rm0, fmaxf(sc[ni][0], sc[ni][1]));
            rm1 = fmaxf(rm1, fmaxf(sc[ni][2], sc[ni][3]));
        }
        rm0 = fmaxf(rm0, __shfl_xor_sync(0xffffffffu, rm0, 1));
        rm0 = fmaxf(rm0, __shfl_xor_sync(0xffffffffu, rm0, 2));
        rm1 = fmaxf(rm1, __shfl_xor_sync(0xffffffffu, rm1, 1));
        rm1 = fmaxf(rm1, __shfl_xor_sync(0xffffffffu, rm1, 2));

        const float mn0 = fmaxf(mr0, rm0);
        const float mn1 = fmaxf(mr1, rm1);
        const float f0 = fast_exp2(mr0 - mn0);
        const float f1 = fast_exp2(mr1 - mn1);
        mr0 = mn0; mr1 = mn1;

        float s0 = 0.f, s1 = 0.f;
        #pragma unroll
        for (int ni = 0; ni < 8; ni++) {
            sc[ni][0] = fast_exp2(sc[ni][0] - mn0);
            sc[ni][1] = fast_exp2(sc[ni][1] - mn0);
            sc[ni][2] = fast_exp2(sc[ni][2] - mn1);
            sc[ni][3] = fast_exp2(sc[ni][3] - mn1);
            s0 += sc[ni][0] + sc[ni][1];
            s1 += sc[ni][2] + sc[ni][3];
        }
        s0 += __shfl_xor_sync(0xffffffffu, s0, 1);
        s0 += __shfl_xor_sync(0xffffffffu, s0, 2);
        s1 += __shfl_xor_sync(0xffffffffu, s1, 1);
        s1 += __shfl_xor_sync(0xffffffffu, s1, 2);

        lr0 = lr0 * f0 + s0;
        lr1 = lr1 * f1 + s1;
        #pragma unroll
        for (int ni = 0; ni < 8; ni++) {
            oa[ni][0] *= f0; oa[ni][1] *= f0;
            oa[ni][2] *= f1; oa[ni][3] *= f1;
        }

        // ---- PV: O += P @ V ; P fragments built by shuffle from sc ----
        #pragma unroll
        for (int kk = 0; kk < 8; kk++) {
            // accum layout -> A-fragment layout: want P[g][kk*8+tig], P[g+8][..],
            // P[g][kk*8+tig+4], P[g+8][..+4]
            float u0 = __shfl_sync(0xffffffffu, sc[kk][0], srcA);
            float u1 = __shfl_sync(0xffffffffu, sc[kk][1], srcA);
            float v0 = __shfl_sync(0xffffffffu, sc[kk][0], srcB);
            float v1 = __shfl_sync(0xffffffffu, sc[kk][1], srcB);
            float w0 = __shfl_sync(0xffffffffu, sc[kk][2], srcA);
            float w1 = __shfl_sync(0xffffffffu, sc[kk][3], srcA);
            float x0 = __shfl_sync(0xffffffffu, sc[kk][2], srcB);
            float x1 = __shfl_sync(0xffffffffu, sc[kk][3], srcB);
            uint32_t pa[4];
            pa[0] = __float_as_uint(to_tf32(odd ? u1 : u0));
            pa[1] = __float_as_uint(to_tf32(odd ? w1 : w0));
            pa[2] = __float_as_uint(to_tf32(odd ? v1 : v0));
            pa[3] = __float_as_uint(to_tf32(odd ? x1 : x0));

            #pragma unroll
            for (int ni = 0; ni < 8; ni++) {
                uint32_t bf[2];
                bf[0] = __float_as_uint(Vs[(kk * 8 + tig)     * VPAD + ni * 8 + g]);
                bf[1] = __float_as_uint(Vs[(kk * 8 + tig + 4) * VPAD + ni * 8 + g]);
                mma_tf32(oa[ni], pa, bf, oa[ni]);
            }
        }
    }

    // ---- epilogue ----
    const float i0 = 1.f / lr0;
    const float i1 = 1.f / lr1;
    float* ob = gout + (size_t)b * SEQ * DM + (size_t)h * DK;
    const int row0 = q0 + m + g;
    #pragma unroll
    for (int ni = 0; ni < 8; ni++) {
        const int col = ni * 8 + 2 * tig;
        *(float2*)&ob[(size_t)row0 * DM + col] =
            make_float2(oa[ni][0] * i0, oa[ni][1] * i0);
        *(float2*)&ob[(size_t)(row0 + 8) * DM + col] =
            make_float2(oa[ni][2] * i1, oa[ni][3] * i1);
    }
}

// ---------------- launch -----------------------------------------------------
extern "C" void kernel_launch(void* const* d_in, const int* in_sizes, int n_in,
                              void* d_out, int out_size)
{
    const float* Q  = (const float*)d_in[0];
    const float* K  = (const float*)d_in[1];
    const float* V  = (const float*)d_in[2];
    const float* Wq = (const float*)d_in[3];
    const float* bq = (const float*)d_in[4];
    const float* Wk = (const float*)d_in[5];
    const float* bk = (const float*)d_in[6];
    const float* Wv = (const float*)d_in[7];
    const float* bv = (const float*)d_in[8];
    const float* Wo = (const float*)d_in[9];
    const float* bo = (const float*)d_in[10];
    float* out = (float*)d_out;

    void *pq, *pk, *pv, *pa;
    cudaGetSymbolAddress(&pq, g_q);
    cudaGetSymbolAddress(&pk, g_k);
    cudaGetSymbolAddress(&pv, g_v);
    cudaGetSymbolAddress(&pa, g_attn);

    static bool attr_set = false;
    if (!attr_set) {
        cudaFuncSetAttribute(attn_tf32,
                             cudaFuncAttributeMaxDynamicSharedMemorySize,
                             (int)ATTN_SMEM);
        attr_set = true;
    }

    dim3 pgrid(DM / 128, MROWS / 128);   // (8, 64)
    dim3 pblock(256);

    gemm_bias_tf32<<<pgrid, pblock>>>(Q, Wq, bq, (float*)pq, MROWS, DM, DM);
    gemm_bias_tf32<<<pgrid, pblock>>>(K, Wk, bk, (float*)pk, MROWS, DM, DM);
    gemm_bias_tf32<<<pgrid, pblock>>>(V, Wv, bv, (float*)pv, MROWS, DM, DM);

    dim3 agrid(SEQ / 64, BATCH * NH);    // (32, 64)
    attn_tf32<<<agrid, 128, ATTN_SMEM>>>((const float*)pq, (const float*)pk,
                                         (const float*)pv, (float*)pa);

    gemm_bias_tf32<<<pgrid, pblock>>>((const float*)pa, Wo, bo, out, MROWS, DM, DM);
}

// round 7
// speedup vs baseline: 1.0342x; 1.0342x over previous
#include <cuda_runtime.h>
#include <cuda_bf16.h>
#include <math.h>
#include <stdint.h>

// Problem constants
#define BATCH 4
#define SEQ   2048
#define DM    1024
#define NH    16
#define DK    64
#define MROWS (BATCH * SEQ)      // 8192

// ---------------- scratch (device globals; no runtime alloc) ----------------
__device__ float g_q[MROWS * DM];
__device__ float g_k[MROWS * DM];
__device__ float g_v[MROWS * DM];
__device__ float g_attn[MROWS * DM];

// ---------------- helpers ----------------------------------------------------
__device__ __forceinline__ float to_tf32(float x) {
    uint32_t u;
    asm("cvt.rna.tf32.f32 %0, %1;" : "=r"(u) : "f"(x));
    return __uint_as_float(u);
}
__device__ __forceinline__ float fast_exp2(float x) {
    float y;
    asm("ex2.approx.f32 %0, %1;" : "=f"(y) : "f"(x));
    return y;
}
// D = A(16x8 tf32, row) * B(8x8 tf32, col) + C   (in-place C allowed)
__device__ __forceinline__ void mma_tf32(float* d, const uint32_t* a,
                                         const uint32_t* b, const float* c) {
    asm volatile(
        "mma.sync.aligned.m16n8k8.row.col.f32.tf32.tf32.f32 "
        "{%0,%1,%2,%3}, {%4,%5,%6,%7}, {%8,%9}, {%10,%11,%12,%13};\n"
        : "=f"(d[0]), "=f"(d[1]), "=f"(d[2]), "=f"(d[3])
        : "r"(a[0]), "r"(a[1]), "r"(a[2]), "r"(a[3]),
          "r"(b[0]), "r"(b[1]),
          "f"(c[0]), "f"(c[1]), "f"(c[2]), "f"(c[3]));
}

// ---------------- tf32 GEMM with bias: C = A[M,K] @ W[K,N] + b ---------------
// 128x128x32 tile, 512 threads (16 warps, 4x4), warp tile 32x32.
// Double-buffered smem, one sync per k-iter, LDG prefetch over compute.
#define APAD 36
#define BPAD 136
#define ABUF (128 * APAD)
#define BBUF (32 * BPAD)
#define GEMM_SMEM ((2 * ABUF + 2 * BBUF) * sizeof(float))

__global__ __launch_bounds__(512) void gemm_bias_tf32(
    const float* __restrict__ A, const float* __restrict__ W,
    const float* __restrict__ bias, float* __restrict__ C,
    int M, int N, int K)
{
    extern __shared__ float gsm[];
    float* As = gsm;                 // [2][128][APAD]
    float* Bs = gsm + 2 * ABUF;      // [2][32][BPAD]

    const int tid  = threadIdx.x;
    const int lane = tid & 31;
    const int warp = tid >> 5;       // 0..15
    const int g    = lane >> 2;
    const int tig  = lane & 3;
    const int wm   = warp >> 2;      // 0..3
    const int wn   = warp & 3;       // 0..3
    const int bm   = blockIdx.y * 128;
    const int bn   = blockIdx.x * 128;

    // load index mapping (per-thread, 2 iterations each)
    int ar[2], ac[2], br[2], bc[2];
    #pragma unroll
    for (int it = 0; it < 2; it++) {
        int idx = tid + 512 * it;
        ar[it] = idx >> 3;  ac[it] = (idx & 7) * 4;
        br[it] = idx >> 5;  bc[it] = (idx & 31) * 4;
    }

    float acc[2][4][4];
    #pragma unroll
    for (int mi = 0; mi < 2; mi++)
        #pragma unroll
        for (int ni = 0; ni < 4; ni++)
            #pragma unroll
            for (int q = 0; q < 4; q++) acc[mi][ni][q] = 0.f;

    float4 pa[2], pb[2];
    // prologue: fetch + commit k-tile 0 into buffer 0
    #pragma unroll
    for (int it = 0; it < 2; it++) {
        pa[it] = *(const float4*)&A[(size_t)(bm + ar[it]) * K + ac[it]];
        pb[it] = *(const float4*)&W[(size_t)br[it] * N + bn + bc[it]];
    }
    #pragma unroll
    for (int it = 0; it < 2; it++) {
        float* p = &As[ar[it] * APAD + ac[it]];
        p[0] = to_tf32(pa[it].x); p[1] = to_tf32(pa[it].y);
        p[2] = to_tf32(pa[it].z); p[3] = to_tf32(pa[it].w);
        float* q = &Bs[br[it] * BPAD + bc[it]];
        q[0] = to_tf32(pb[it].x); q[1] = to_tf32(pb[it].y);
        q[2] = to_tf32(pb[it].z); q[3] = to_tf32(pb[it].w);
    }
    __syncthreads();

    const int NITER = K / 32;
    for (int t = 0; t < NITER; t++) {
        const int cur = t & 1, nxt = cur ^ 1;
        const float* Ac = As + cur * ABUF;
        const float* Bc = Bs + cur * BBUF;

        // issue next tile's LDGs; latency hides under the MMAs below
        if (t + 1 < NITER) {
            const int k0 = (t + 1) * 32;
            #pragma unroll
            for (int it = 0; it < 2; it++) {
                pa[it] = *(const float4*)&A[(size_t)(bm + ar[it]) * K + k0 + ac[it]];
                pb[it] = *(const float4*)&W[(size_t)(k0 + br[it]) * N + bn + bc[it]];
            }
        }

        // compute current tile
        #pragma unroll
        for (int kk = 0; kk < 4; kk++) {
            uint32_t af[2][4];
            #pragma unroll
            for (int mi = 0; mi < 2; mi++) {
                const int m = wm * 32 + mi * 16;
                af[mi][0] = __float_as_uint(Ac[(m + g)     * APAD + kk * 8 + tig]);
                af[mi][1] = __float_as_uint(Ac[(m + g + 8) * APAD + kk * 8 + tig]);
                af[mi][2] = __float_as_uint(Ac[(m + g)     * APAD + kk * 8 + tig + 4]);
                af[mi][3] = __float_as_uint(Ac[(m + g + 8) * APAD + kk * 8 + tig + 4]);
            }
            #pragma unroll
            for (int ni = 0; ni < 4; ni++) {
                const int n = wn * 32 + ni * 8;
                uint32_t bf[2];
                bf[0] = __float_as_uint(Bc[(kk * 8 + tig)     * BPAD + n + g]);
                bf[1] = __float_as_uint(Bc[(kk * 8 + tig + 4) * BPAD + n + g]);
                #pragma unroll
                for (int mi = 0; mi < 2; mi++)
                    mma_tf32(acc[mi][ni], af[mi], bf, acc[mi][ni]);
            }
        }

        // commit next tile into the other buffer
        if (t + 1 < NITER) {
            float* An = As + nxt * ABUF;
            float* Bn = Bs + nxt * BBUF;
            #pragma unroll
            for (int it = 0; it < 2; it++) {
                float* p = &An[ar[it] * APAD + ac[it]];
                p[0] = to_tf32(pa[it].x); p[1] = to_tf32(pa[it].y);
                p[2] = to_tf32(pa[it].z); p[3] = to_tf32(pa[it].w);
                float* q = &Bn[br[it] * BPAD + bc[it]];
                q[0] = to_tf32(pb[it].x); q[1] = to_tf32(pb[it].y);
                q[2] = to_tf32(pb[it].z); q[3] = to_tf32(pb[it].w);
            }
        }
        __syncthreads();
    }

    // epilogue: bias add, float2 stores
    #pragma unroll
    for (int mi = 0; mi < 2; mi++) {
        const int row = bm + wm * 32 + mi * 16 + g;
        #pragma unroll
        for (int ni = 0; ni < 4; ni++) {
            const int col = bn + wn * 32 + ni * 8 + 2 * tig;
            const float b0 = bias[col], b1 = bias[col + 1];
            float2 o0 = make_float2(acc[mi][ni][0] + b0, acc[mi][ni][1] + b1);
            float2 o1 = make_float2(acc[mi][ni][2] + b0, acc[mi][ni][3] + b1);
            *(float2*)&C[(size_t)row * N + col]       = o0;
            *(float2*)&C[(size_t)(row + 8) * N + col] = o1;
        }
    }
}

// ---------------- tf32 flash attention (R4 version, known-good) --------------
// Block: 128 threads (4 warps). BQ=64 q-rows (warp owns 16), BKV=64.
// smem: QP[64][76] (Q then P), Ks[64][76], Vs[64][72]
#define QPAD 76
#define VPAD 72
#define ATTN_SMEM ((64 * QPAD + 64 * QPAD + 64 * VPAD) * sizeof(float))

__global__ __launch_bounds__(128) void attn_tf32(
    const float* __restrict__ gq, const float* __restrict__ gk,
    const float* __restrict__ gv, float* __restrict__ gout)
{
    extern __shared__ float smf[];
    float* QP = smf;                   // [64][QPAD]  Q tile, reused for P
    float* Ks = QP + 64 * QPAD;        // [64][QPAD]
    float* Vs = Ks + 64 * QPAD;        // [64][VPAD]

    const int tid  = threadIdx.x;
    const int lane = tid & 31;
    const int warp = tid >> 5;         // 0..3
    const int g    = lane >> 2;
    const int tig  = lane & 3;
    const int q0   = blockIdx.x * 64;
    const int b    = blockIdx.y >> 4;
    const int h    = blockIdx.y & 15;

    const float* qb = gq + (size_t)b * SEQ * DM + (size_t)h * DK;
    const float* kb = gk + (size_t)b * SEQ * DM + (size_t)h * DK;
    const float* vb = gv + (size_t)b * SEQ * DM + (size_t)h * DK;

    // scale (1/sqrt(64)) * log2(e): softmax done in base-2
    const float qscale = 0.125f * 1.44269504f;

    // Load Q tile (scaled, tf32) : 64 rows x 16 float4
    for (int i = tid; i < 64 * 16; i += 128) {
        int r = i >> 4, c4 = (i & 15) * 4;
        float4 v = *(const float4*)&qb[(size_t)(q0 + r) * DM + c4];
        float* p = &QP[r * QPAD + c4];
        p[0] = to_tf32(v.x * qscale); p[1] = to_tf32(v.y * qscale);
        p[2] = to_tf32(v.z * qscale); p[3] = to_tf32(v.w * qscale);
    }
    __syncthreads();

    // Q fragments to registers (constant across all KV tiles)
    const int m = warp * 16;
    uint32_t qa[8][4];
    #pragma unroll
    for (int kk = 0; kk < 8; kk++) {
        qa[kk][0] = __float_as_uint(QP[(m + g)     * QPAD + kk * 8 + tig]);
        qa[kk][1] = __float_as_uint(QP[(m + g + 8) * QPAD + kk * 8 + tig]);
        qa[kk][2] = __float_as_uint(QP[(m + g)     * QPAD + kk * 8 + tig + 4]);
        qa[kk][3] = __float_as_uint(QP[(m + g + 8) * QPAD + kk * 8 + tig + 4]);
    }
    __syncthreads();   // all warps done reading Q before QP becomes P

    float oa[8][4];
    #pragma unroll
    for (int ni = 0; ni < 8; ni++)
        #pragma unroll
        for (int q = 0; q < 4; q++) oa[ni][q] = 0.f;
    float mr0 = -1e30f, mr1 = -1e30f, lr0 = 0.f, lr1 = 0.f;

    for (int kt = 0; kt < SEQ / 64; kt++) {
        const int j0 = kt * 64;
        __syncthreads();   // prior PV reads of Ks/Vs complete

        for (int i = tid; i < 64 * 16; i += 128) {
            int r = i >> 4, c4 = (i & 15) * 4;
            float4 kv = *(const float4*)&kb[(size_t)(j0 + r) * DM + c4];
            float4 vv = *(const float4*)&vb[(size_t)(j0 + r) * DM + c4];
            float* pk = &Ks[r * QPAD + c4];
            pk[0] = to_tf32(kv.x); pk[1] = to_tf32(kv.y);
            pk[2] = to_tf32(kv.z); pk[3] = to_tf32(kv.w);
            float* pv = &Vs[r * VPAD + c4];
            pv[0] = to_tf32(vv.x); pv[1] = to_tf32(vv.y);
            pv[2] = to_tf32(vv.z); pv[3] = to_tf32(vv.w);
        }
        __syncthreads();

        // ---- scores: S[r][j] = Q.K  (16 rows x 64 cols per warp) ----
        float sc[8][4];
        #pragma unroll
        for (int ni = 0; ni < 8; ni++)
            #pragma unroll
            for (int q = 0; q < 4; q++) sc[ni][q] = 0.f;

        #pragma unroll
        for (int kk = 0; kk < 8; kk++) {
            #pragma unroll
            for (int ni = 0; ni < 8; ni++) {
                uint32_t bf[2];
                bf[0] = __float_as_uint(Ks[(ni * 8 + g) * QPAD + kk * 8 + tig]);
                bf[1] = __float_as_uint(Ks[(ni * 8 + g) * QPAD + kk * 8 + tig + 4]);
                mma_tf32(sc[ni], qa[kk], bf, sc[ni]);
            }
        }

        // ---- online softmax (base 2) ----
        float rm0 = -1e30f, rm1 = -1e30f;
        #pragma unroll
        for (int ni = 0; ni < 8; ni++) {
            rm0 = fmaxf(rm0, fmaxf(sc[ni][0], sc[ni][1]));
            rm1 = fmaxf(rm1, fmaxf(sc[ni][2], sc[ni][3]));
        }
        rm0 = fmaxf(rm0, __shfl_xor_sync(0xffffffffu, rm0, 1));
        rm0 = fmaxf(rm0, __shfl_xor_sync(0xffffffffu, rm0, 2));
        rm1 = fmaxf(rm1, __shfl_xor_sync(0xffffffffu, rm1, 1));
        rm1 = fmaxf(rm1, __shfl_xor_sync(0xffffffffu, rm1, 2));

        const float mn0 = fmaxf(mr0, rm0);
        const float mn1 = fmaxf(mr1, rm1);
        const float f0 = fast_exp2(mr0 - mn0);
        const float f1 = fast_exp2(mr1 - mn1);
        mr0 = mn0; mr1 = mn1;

        float s0 = 0.f, s1 = 0.f;
        #pragma unroll
        for (int ni = 0; ni < 8; ni++) {
            sc[ni][0] = fast_exp2(sc[ni][0] - mn0);
            sc[ni][1] = fast_exp2(sc[ni][1] - mn0);
            sc[ni][2] = fast_exp2(sc[ni][2] - mn1);
            sc[ni][3] = fast_exp2(sc[ni][3] - mn1);
            s0 += sc[ni][0] + sc[ni][1];
            s1 += sc[ni][2] + sc[ni][3];
        }
        s0 += __shfl_xor_sync(0xffffffffu, s0, 1);
        s0 += __shfl_xor_sync(0xffffffffu, s0, 2);
        s1 += __shfl_xor_sync(0xffffffffu, s1, 1);
        s1 += __shfl_xor_sync(0xffffffffu, s1, 2);

        lr0 = lr0 * f0 + s0;
        lr1 = lr1 * f1 + s1;
        #pragma unroll
        for (int ni = 0; ni < 8; ni++) {
            oa[ni][0] *= f0; oa[ni][1] *= f0;
            oa[ni][2] *= f1; oa[ni][3] *= f1;
        }

        // ---- stage P (warp-private rows of QP) ----
        #pragma unroll
        for (int ni = 0; ni < 8; ni++) {
            const int col = ni * 8 + 2 * tig;
            *(float2*)&QP[(m + g) * QPAD + col] =
                make_float2(to_tf32(sc[ni][0]), to_tf32(sc[ni][1]));
            *(float2*)&QP[(m + g + 8) * QPAD + col] =
                make_float2(to_tf32(sc[ni][2]), to_tf32(sc[ni][3]));
        }
        __syncwarp();

        // ---- PV: O += P @ V ----
        #pragma unroll
        for (int kk = 0; kk < 8; kk++) {
            uint32_t pa[4];
            pa[0] = __float_as_uint(QP[(m + g)     * QPAD + kk * 8 + tig]);
            pa[1] = __float_as_uint(QP[(m + g + 8) * QPAD + kk * 8 + tig]);
            pa[2] = __float_as_uint(QP[(m + g)     * QPAD + kk * 8 + tig + 4]);
            pa[3] = __float_as_uint(QP[(m + g + 8) * QPAD + kk * 8 + tig + 4]);
            #pragma unroll
            for (int ni = 0; ni < 8; ni++) {
                uint32_t bf[2];
                bf[0] = __float_as_uint(Vs[(kk * 8 + tig)     * VPAD + ni * 8 + g]);
                bf[1] = __float_as_uint(Vs[(kk * 8 + tig + 4) * VPAD + ni * 8 + g]);
                mma_tf32(oa[ni], pa, bf, oa[ni]);
            }
        }
        __syncwarp();   // P reads done before next iteration overwrites
    }

    // ---- epilogue ----
    const float i0 = 1.f / lr0;
    const float i1 = 1.f / lr1;
    float* ob = gout + (size_t)b * SEQ * DM + (size_t)h * DK;
    const int row0 = q0 + m + g;
    #pragma unroll
    for (int ni = 0; ni < 8; ni++) {
        const int col = ni * 8 + 2 * tig;
        *(float2*)&ob[(size_t)row0 * DM + col] =
            make_float2(oa[ni][0] * i0, oa[ni][1] * i0);
        *(float2*)&ob[(size_t)(row0 + 8) * DM + col] =
            make_float2(oa[ni][2] * i1, oa[ni][3] * i1);
    }
}

// ---------------- launch -----------------------------------------------------
extern "C" void kernel_launch(void* const* d_in, const int* in_sizes, int n_in,
                              void* d_out, int out_size)
{
    const float* Q  = (const float*)d_in[0];
    const float* K  = (const float*)d_in[1];
    const float* V  = (const float*)d_in[2];
    const float* Wq = (const float*)d_in[3];
    const float* bq = (const float*)d_in[4];
    const float* Wk = (const float*)d_in[5];
    const float* bk = (const float*)d_in[6];
    const float* Wv = (const float*)d_in[7];
    const float* bv = (const float*)d_in[8];
    const float* Wo = (const float*)d_in[9];
    const float* bo = (const float*)d_in[10];
    float* out = (float*)d_out;

    void *pq, *pk, *pv, *pa;
    cudaGetSymbolAddress(&pq, g_q);
    cudaGetSymbolAddress(&pk, g_k);
    cudaGetSymbolAddress(&pv, g_v);
    cudaGetSymbolAddress(&pa, g_attn);

    static bool attr_set = false;
    if (!attr_set) {
        cudaFuncSetAttribute(attn_tf32,
                             cudaFuncAttributeMaxDynamicSharedMemorySize,
                             (int)ATTN_SMEM);
        cudaFuncSetAttribute(gemm_bias_tf32,
                             cudaFuncAttributeMaxDynamicSharedMemorySize,
                             (int)GEMM_SMEM);
        attr_set = true;
    }

    dim3 pgrid(DM / 128, MROWS / 128);   // (8, 64)
    dim3 pblock(512);

    gemm_bias_tf32<<<pgrid, pblock, GEMM_SMEM>>>(Q, Wq, bq, (float*)pq, MROWS, DM, DM);
    gemm_bias_tf32<<<pgrid, pblock, GEMM_SMEM>>>(K, Wk, bk, (float*)pk, MROWS, DM, DM);
    gemm_bias_tf32<<<pgrid, pblock, GEMM_SMEM>>>(V, Wv, bv, (float*)pv, MROWS, DM, DM);

    dim3 agrid(SEQ / 64, BATCH * NH);    // (32, 64)
    attn_tf32<<<agrid, 128, ATTN_SMEM>>>((const float*)pq, (const float*)pk,
                                         (const float*)pv, (float*)pa);

    gemm_bias_tf32<<<pgrid, pblock, GEMM_SMEM>>>((const float*)pa, Wo, bo, out, MROWS, DM, DM);
}

// round 10
// speedup vs baseline: 1.0900x; 1.0540x over previous
#include <cuda_runtime.h>
#include <cuda_bf16.h>
#include <math.h>
#include <stdint.h>

// Problem constants
#define BATCH 4
#define SEQ   2048
#define DM    1024
#define NH    16
#define DK    64
#define MROWS (BATCH * SEQ)      // 8192

// ---------------- scratch (device globals; no runtime alloc) ----------------
__device__ float g_q[MROWS * DM];
__device__ float g_k[MROWS * DM];
__device__ float g_v[MROWS * DM];
__device__ float g_attn[MROWS * DM];

// ---------------- helpers ----------------------------------------------------
__device__ __forceinline__ float to_tf32(float x) {
    uint32_t u;
    asm("cvt.rna.tf32.f32 %0, %1;" : "=r"(u) : "f"(x));
    return __uint_as_float(u);
}
__device__ __forceinline__ float fast_exp2(float x) {
    float y;
    asm("ex2.approx.f32 %0, %1;" : "=f"(y) : "f"(x));
    return y;
}
// D = A(16x8 tf32, row) * B(8x8 tf32, col) + C   (in-place C allowed)
__device__ __forceinline__ void mma_tf32(float* d, const uint32_t* a,
                                         const uint32_t* b, const float* c) {
    asm volatile(
        "mma.sync.aligned.m16n8k8.row.col.f32.tf32.tf32.f32 "
        "{%0,%1,%2,%3}, {%4,%5,%6,%7}, {%8,%9}, {%10,%11,%12,%13};\n"
        : "=f"(d[0]), "=f"(d[1]), "=f"(d[2]), "=f"(d[3])
        : "r"(a[0]), "r"(a[1]), "r"(a[2]), "r"(a[3]),
          "r"(b[0]), "r"(b[1]),
          "f"(c[0]), "f"(c[1]), "f"(c[2]), "f"(c[3]));
}

// ---------------- tf32 GEMM with bias: C = A[M,K] @ W[K,N] + b ---------------
// EXACT R4 version (measured-good): 128x128x32 tile, 256 threads (8 warps 2x4),
// warp tile 64x32, static smem, serial k-loop.
#define APAD 36
#define BPAD 136

__global__ __launch_bounds__(256) void gemm_bias_tf32(
    const float* __restrict__ A, const float* __restrict__ W,
    const float* __restrict__ bias, float* __restrict__ C,
    int M, int N, int K)
{
    __shared__ float As[128 * APAD];   // [m][k] pad 36
    __shared__ float Bs[32 * BPAD];    // [k][n] pad 136

    const int tid  = threadIdx.x;
    const int lane = tid & 31;
    const int warp = tid >> 5;
    const int g    = lane >> 2;
    const int tig  = lane & 3;
    const int wm   = warp >> 2;        // 0..1
    const int wn   = warp & 3;         // 0..3
    const int bm   = blockIdx.y * 128;
    const int bn   = blockIdx.x * 128;

    float acc[4][4][4];
    #pragma unroll
    for (int mi = 0; mi < 4; mi++)
        #pragma unroll
        for (int ni = 0; ni < 4; ni++)
            #pragma unroll
            for (int q = 0; q < 4; q++) acc[mi][ni][q] = 0.f;

    for (int k0 = 0; k0 < K; k0 += 32) {
        // A tile: 128 rows x 32 k  (1024 float4)
        #pragma unroll
        for (int it = 0; it < 4; it++) {
            int idx = tid + 256 * it;
            int r = idx >> 3, c4 = (idx & 7) * 4;
            float4 v = *(const float4*)&A[(size_t)(bm + r) * K + k0 + c4];
            float* p = &As[r * APAD + c4];
            p[0] = to_tf32(v.x); p[1] = to_tf32(v.y);
            p[2] = to_tf32(v.z); p[3] = to_tf32(v.w);
        }
        // B tile: 32 rows x 128 n
        #pragma unroll
        for (int it = 0; it < 4; it++) {
            int idx = tid + 256 * it;
            int r = idx >> 5, c4 = (idx & 31) * 4;
            float4 v = *(const float4*)&W[(size_t)(k0 + r) * N + bn + c4];
            float* p = &Bs[r * BPAD + c4];
            p[0] = to_tf32(v.x); p[1] = to_tf32(v.y);
            p[2] = to_tf32(v.z); p[3] = to_tf32(v.w);
        }
        __syncthreads();

        #pragma unroll
        for (int kk = 0; kk < 4; kk++) {
            uint32_t af[4][4];
            #pragma unroll
            for (int mi = 0; mi < 4; mi++) {
                const int m = wm * 64 + mi * 16;
                af[mi][0] = __float_as_uint(As[(m + g)     * APAD + kk * 8 + tig]);
                af[mi][1] = __float_as_uint(As[(m + g + 8) * APAD + kk * 8 + tig]);
                af[mi][2] = __float_as_uint(As[(m + g)     * APAD + kk * 8 + tig + 4]);
                af[mi][3] = __float_as_uint(As[(m + g + 8) * APAD + kk * 8 + tig + 4]);
            }
            #pragma unroll
            for (int ni = 0; ni < 4; ni++) {
                const int n = wn * 32 + ni * 8;
                uint32_t bf[2];
                bf[0] = __float_as_uint(Bs[(kk * 8 + tig)     * BPAD + n + g]);
                bf[1] = __float_as_uint(Bs[(kk * 8 + tig + 4) * BPAD + n + g]);
                #pragma unroll
                for (int mi = 0; mi < 4; mi++)
                    mma_tf32(acc[mi][ni], af[mi], bf, acc[mi][ni]);
            }
        }
        __syncthreads();
    }

    // epilogue: bias add, float2 stores
    #pragma unroll
    for (int mi = 0; mi < 4; mi++) {
        const int row = bm + wm * 64 + mi * 16 + g;
        #pragma unroll
        for (int ni = 0; ni < 4; ni++) {
            const int col = bn + wn * 32 + ni * 8 + 2 * tig;
            const float b0 = bias[col], b1 = bias[col + 1];
            float2 o0 = make_float2(acc[mi][ni][0] + b0, acc[mi][ni][1] + b1);
            float2 o1 = make_float2(acc[mi][ni][2] + b0, acc[mi][ni][3] + b1);
            *(float2*)&C[(size_t)row * N + col]       = o0;
            *(float2*)&C[(size_t)(row + 8) * N + col] = o1;
        }
    }
}

// ---------------- tf32 flash attention --------------------------------------
// 256 threads (8 warps), BQ=128 (warp owns 16 q-rows), BKV=64.
// Per-warp math identical to the measured-good R4 kernel; K/V tile now shared
// by 8 warps (gmem traffic halves, occupancy up).
// smem: QP[128][76] (Q then P), Ks[64][76], Vs[64][72]
#define QPAD 76
#define VPAD 72
#define ATTN_SMEM ((128 * QPAD + 64 * QPAD + 64 * VPAD) * sizeof(float))

__global__ __launch_bounds__(256) void attn_tf32(
    const float* __restrict__ gq, const float* __restrict__ gk,
    const float* __restrict__ gv, float* __restrict__ gout)
{
    extern __shared__ float smf[];
    float* QP = smf;                    // [128][QPAD]  Q tile, reused for P
    float* Ks = QP + 128 * QPAD;        // [64][QPAD]
    float* Vs = Ks + 64 * QPAD;         // [64][VPAD]

    const int tid  = threadIdx.x;
    const int lane = tid & 31;
    const int warp = tid >> 5;          // 0..7
    const int g    = lane >> 2;
    const int tig  = lane & 3;
    const int q0   = blockIdx.x * 128;
    const int b    = blockIdx.y >> 4;
    const int h    = blockIdx.y & 15;

    const float* qb = gq + (size_t)b * SEQ * DM + (size_t)h * DK;
    const float* kb = gk + (size_t)b * SEQ * DM + (size_t)h * DK;
    const float* vb = gv + (size_t)b * SEQ * DM + (size_t)h * DK;

    // scale (1/sqrt(64)) * log2(e): softmax done in base-2
    const float qscale = 0.125f * 1.44269504f;

    // Load Q tile (scaled, tf32): 128 rows x 16 float4
    for (int i = tid; i < 128 * 16; i += 256) {
        int r = i >> 4, c4 = (i & 15) * 4;
        float4 v = *(const float4*)&qb[(size_t)(q0 + r) * DM + c4];
        float* p = &QP[r * QPAD + c4];
        p[0] = to_tf32(v.x * qscale); p[1] = to_tf32(v.y * qscale);
        p[2] = to_tf32(v.z * qscale); p[3] = to_tf32(v.w * qscale);
    }
    __syncthreads();

    // Q fragments to registers (constant across all KV tiles)
    const int m = warp * 16;
    uint32_t qa[8][4];
    #pragma unroll
    for (int kk = 0; kk < 8; kk++) {
        qa[kk][0] = __float_as_uint(QP[(m + g)     * QPAD + kk * 8 + tig]);
        qa[kk][1] = __float_as_uint(QP[(m + g + 8) * QPAD + kk * 8 + tig]);
        qa[kk][2] = __float_as_uint(QP[(m + g)     * QPAD + kk * 8 + tig + 4]);
        qa[kk][3] = __float_as_uint(QP[(m + g + 8) * QPAD + kk * 8 + tig + 4]);
    }
    __syncthreads();   // all warps done reading Q before QP becomes P

    float oa[8][4];
    #pragma unroll
    for (int ni = 0; ni < 8; ni++)
        #pragma unroll
        for (int q = 0; q < 4; q++) oa[ni][q] = 0.f;
    float mr0 = -1e30f, mr1 = -1e30f, lr0 = 0.f, lr1 = 0.f;

    for (int kt = 0; kt < SEQ / 64; kt++) {
        const int j0 = kt * 64;
        __syncthreads();   // prior PV reads of Ks/Vs complete

        for (int i = tid; i < 64 * 16; i += 256) {
            int r = i >> 4, c4 = (i & 15) * 4;
            float4 kv = *(const float4*)&kb[(size_t)(j0 + r) * DM + c4];
            float4 vv = *(const float4*)&vb[(size_t)(j0 + r) * DM + c4];
            float* pk = &Ks[r * QPAD + c4];
            pk[0] = to_tf32(kv.x); pk[1] = to_tf32(kv.y);
            pk[2] = to_tf32(kv.z); pk[3] = to_tf32(kv.w);
            float* pv = &Vs[r * VPAD + c4];
            pv[0] = to_tf32(vv.x); pv[1] = to_tf32(vv.y);
            pv[2] = to_tf32(vv.z); pv[3] = to_tf32(vv.w);
        }
        __syncthreads();

        // ---- scores: S[r][j] = Q.K  (16 rows x 64 cols per warp) ----
        float sc[8][4];
        #pragma unroll
        for (int ni = 0; ni < 8; ni++)
            #pragma unroll
            for (int q = 0; q < 4; q++) sc[ni][q] = 0.f;

        #pragma unroll
        for (int kk = 0; kk < 8; kk++) {
            #pragma unroll
            for (int ni = 0; ni < 8; ni++) {
                uint32_t bf[2];
                bf[0] = __float_as_uint(Ks[(ni * 8 + g) * QPAD + kk * 8 + tig]);
                bf[1] = __float_as_uint(Ks[(ni * 8 + g) * QPAD + kk * 8 + tig + 4]);
                mma_tf32(sc[ni], qa[kk], bf, sc[ni]);
            }
        }

        // ---- online softmax (base 2) ----
        float rm0 = -1e30f, rm1 = -1e30f;
        #pragma unroll
        for (int ni = 0; ni < 8; ni++) {
            rm0 = fmaxf(rm0, fmaxf(sc[ni][0], sc[ni][1]));
            rm1 = fmaxf(rm1, fmaxf(sc[ni][2], sc[ni][3]));
        }
        rm0 = fmaxf(rm0, __shfl_xor_sync(0xffffffffu, rm0, 1));
        rm0 = fmaxf(rm0, __shfl_xor_sync(0xffffffffu, rm0, 2));
        rm1 = fmaxf(rm1, __shfl_xor_sync(0xffffffffu, rm1, 1));
        rm1 = fmaxf(rm1, __shfl_xor_sync(0xffffffffu, rm1, 2));

        const float mn0 = fmaxf(mr0, rm0);
        const float mn1 = fmaxf(mr1, rm1);
        const float f0 = fast_exp2(mr0 - mn0);
        const float f1 = fast_exp2(mr1 - mn1);
        mr0 = mn0; mr1 = mn1;

        float s0 = 0.f, s1 = 0.f;
        #pragma unroll
        for (int ni = 0; ni < 8; ni++) {
            sc[ni][0] = fast_exp2(sc[ni][0] - mn0);
            sc[ni][1] = fast_exp2(sc[ni][1] - mn0);
            sc[ni][2] = fast_exp2(sc[ni][2] - mn1);
            sc[ni][3] = fast_exp2(sc[ni][3] - mn1);
            s0 += sc[ni][0] + sc[ni][1];
            s1 += sc[ni][2] + sc[ni][3];
        }
        s0 += __shfl_xor_sync(0xffffffffu, s0, 1);
        s0 += __shfl_xor_sync(0xffffffffu, s0, 2);
        s1 += __shfl_xor_sync(0xffffffffu, s1, 1);
        s1 += __shfl_xor_sync(0xffffffffu, s1, 2);

        lr0 = lr0 * f0 + s0;
        lr1 = lr1 * f1 + s1;
        #pragma unroll
        for (int ni = 0; ni < 8; ni++) {
            oa[ni][0] *= f0; oa[ni][1] *= f0;
            oa[ni][2] *= f1; oa[ni][3] *= f1;
        }

        // ---- stage P (warp-private rows of QP) ----
        #pragma unroll
        for (int ni = 0; ni < 8; ni++) {
            const int col = ni * 8 + 2 * tig;
            *(float2*)&QP[(m + g) * QPAD + col] =
                make_float2(to_tf32(sc[ni][0]), to_tf32(sc[ni][1]));
            *(float2*)&QP[(m + g + 8) * QPAD + col] =
                make_float2(to_tf32(sc[ni][2]), to_tf32(sc[ni][3]));
        }
        __syncwarp();

        // ---- PV: O += P @ V ----
        #pragma unroll
        for (int kk = 0; kk < 8; kk++) {
            uint32_t pa[4];
            pa[0] = __float_as_uint(QP[(m + g)     * QPAD + kk * 8 + tig]);
            pa[1] = __float_as_uint(QP[(m + g + 8) * QPAD + kk * 8 + tig]);
            pa[2] = __float_as_uint(QP[(m + g)     * QPAD + kk * 8 + tig + 4]);
            pa[3] = __float_as_uint(QP[(m + g + 8) * QPAD + kk * 8 + tig + 4]);
            #pragma unroll
            for (int ni = 0; ni < 8; ni++) {
                uint32_t bf[2];
                bf[0] = __float_as_uint(Vs[(kk * 8 + tig)     * VPAD + ni * 8 + g]);
                bf[1] = __float_as_uint(Vs[(kk * 8 + tig + 4) * VPAD + ni * 8 + g]);
                mma_tf32(oa[ni], pa, bf, oa[ni]);
            }
        }
        __syncwarp();   // P reads done before next iteration overwrites
    }

    // ---- epilogue ----
    const float i0 = 1.f / lr0;
    const float i1 = 1.f / lr1;
    float* ob = gout + (size_t)b * SEQ * DM + (size_t)h * DK;
    const int row0 = q0 + m + g;
    #pragma unroll
    for (int ni = 0; ni < 8; ni++) {
        const int col = ni * 8 + 2 * tig;
        *(float2*)&ob[(size_t)row0 * DM + col] =
            make_float2(oa[ni][0] * i0, oa[ni][1] * i0);
        *(float2*)&ob[(size_t)(row0 + 8) * DM + col] =
            make_float2(oa[ni][2] * i1, oa[ni][3] * i1);
    }
}

// ---------------- launch -----------------------------------------------------
extern "C" void kernel_launch(void* const* d_in, const int* in_sizes, int n_in,
                              void* d_out, int out_size)
{
    const float* Q  = (const float*)d_in[0];
    const float* K  = (const float*)d_in[1];
    const float* V  = (const float*)d_in[2];
    const float* Wq = (const float*)d_in[3];
    const float* bq = (const float*)d_in[4];
    const float* Wk = (const float*)d_in[5];
    const float* bk = (const float*)d_in[6];
    const float* Wv = (const float*)d_in[7];
    const float* bv = (const float*)d_in[8];
    const float* Wo = (const float*)d_in[9];
    const float* bo = (const float*)d_in[10];
    float* out = (float*)d_out;

    void *pq, *pk, *pv, *pa;
    cudaGetSymbolAddress(&pq, g_q);
    cudaGetSymbolAddress(&pk, g_k);
    cudaGetSymbolAddress(&pv, g_v);
    cudaGetSymbolAddress(&pa, g_attn);

    static bool attr_set = false;
    if (!attr_set) {
        cudaFuncSetAttribute(attn_tf32,
                             cudaFuncAttributeMaxDynamicSharedMemorySize,
                             (int)ATTN_SMEM);
        attr_set = true;
    }

    dim3 pgrid(DM / 128, MROWS / 128);   // (8, 64)
    dim3 pblock(256);

    gemm_bias_tf32<<<pgrid, pblock>>>(Q, Wq, bq, (float*)pq, MROWS, DM, DM);
    gemm_bias_tf32<<<pgrid, pblock>>>(K, Wk, bk, (float*)pk, MROWS, DM, DM);
    gemm_bias_tf32<<<pgrid, pblock>>>(V, Wv, bv, (float*)pv, MROWS, DM, DM);

    dim3 agrid(SEQ / 128, BATCH * NH);   // (16, 64)
    attn_tf32<<<agrid, 256, ATTN_SMEM>>>((const float*)pq, (const float*)pk,
                                         (const float*)pv, (float*)pa);

    gemm_bias_tf32<<<pgrid, pblock>>>((const float*)pa, Wo, bo, out, MROWS, DM, DM);
}